// round 15
// baseline (speedup 1.0000x reference)
#include <cuda_runtime.h>
#include <math.h>

#define PNT 20
#define KNN 8
#define D0  128
#define MAXN 8192
typedef unsigned long long ull;

__device__ float g_act[ (size_t)MAXN*PNT*512 ];   // activations (widest 512)
__device__ float g_tmp[ (size_t)MAXN*PNT*512 ];   // xagg scratch (widest 512)

__device__ __forceinline__ ull pack2f(float x, float y){
    return ((ull)__float_as_uint(y) << 32) | (ull)__float_as_uint(x);
}
__device__ __forceinline__ ull ffma2(ull a, ull b, ull c){
    ull d;
    asm("fma.rn.f32x2 %0, %1, %2, %3;" : "=l"(d) : "l"(a), "l"(b), "l"(c));
    return d;
}
__device__ __forceinline__ float lo2(ull v){ return __uint_as_float((unsigned)(v & 0xffffffffull)); }
__device__ __forceinline__ float hi2(ull v){ return __uint_as_float((unsigned)(v >> 32)); }
__device__ __forceinline__ float warp_sum(float v){
    #pragma unroll
    for(int m=16;m>0;m>>=1) v += __shfl_xor_sync(0xffffffffu, v, m);
    return v;
}

// ============================================================================
// sgemm: FROZEN R14 version (746us on L2 shape, fma 72.9%).
// 128x128x16 tiles, triple-buffered smem, prefetch distance 2.
// ============================================================================
#define AS_FLOATS (16*132)
#define BS_FLOATS (16*128)
#define SGEMM_SMEM ((3*AS_FLOATS + 3*BS_FLOATS)*4)

__device__ __forceinline__ void gemm_block16(const float* __restrict__ Ab,
                                             const float* __restrict__ Bb,
                                             int mb, int nb, ull (&acc)[4][8]){
    #pragma unroll
    for(int k=0;k<16;k++){
        ulonglong2 a01 = *(const ulonglong2*)&Ab[k*132+mb];
        ulonglong2 a23 = *(const ulonglong2*)&Ab[k*132+mb+16];
        float4 q0 = *(const float4*)&Bb[k*128+nb];
        float4 q1 = *(const float4*)&Bb[k*128+nb+32];
        ull am[4] = {a01.x, a01.y, a23.x, a23.y};
        float bb[8] = {q0.x,q0.y,q0.z,q0.w, q1.x,q1.y,q1.z,q1.w};
        #pragma unroll
        for(int c=0;c<8;c++){
            ull w = pack2f(bb[c], bb[c]);
            #pragma unroll
            for(int r=0;r<4;r++) acc[r][c] = ffma2(am[r], w, acc[r][c]);
        }
    }
}

__device__ __forceinline__ void stage_store(float* __restrict__ Ab, float* __restrict__ Bb,
    int ar, int ac, int br, int bc,
    const float4& a0, const float4& a1, const float4& b0, const float4& b1){
    Ab[(ac+0)*132+ar] = a0.x; Ab[(ac+1)*132+ar] = a0.y;
    Ab[(ac+2)*132+ar] = a0.z; Ab[(ac+3)*132+ar] = a0.w;
    Ab[(ac+0)*132+ar+64] = a1.x; Ab[(ac+1)*132+ar+64] = a1.y;
    Ab[(ac+2)*132+ar+64] = a1.z; Ab[(ac+3)*132+ar+64] = a1.w;
    *(float4*)&Bb[br*128+bc]     = b0;
    *(float4*)&Bb[(br+8)*128+bc] = b1;
}

template<bool EPI>
__global__ void __launch_bounds__(256,2)
sgemm_kernel(const float* __restrict__ A, const float* __restrict__ B,
             const float* __restrict__ bias, float* __restrict__ C,
             int M, int N, int K)
{
    extern __shared__ __align__(16) char sg[];
    float* Asm = (float*)sg;                         // [3][16][132]
    float* Bsm = (float*)(sg + 3*AS_FLOATS*4);       // [3][16][128]

    const int tid = threadIdx.x;
    const int warp = tid >> 5, lane = tid & 31;
    const int wm = warp >> 1, wn = warp & 1;
    const int lm = lane & 3,  ln = lane >> 2;
    const int m0 = blockIdx.y * 128, n0 = blockIdx.x * 128;
    const int ar = tid >> 2, ac = (tid & 3) * 4;
    const int br = tid >> 5, bc = (tid & 31) * 4;

    const float* Ag = A + (long long)(m0 + ar) * K + ac;
    const float* Bg = B + (long long)br * N + (n0 + bc);

    #define LOADT(da0,da1,db0,db1,tt) { \
        const float* Ag2 = Ag + (tt)*16; \
        const float* Bg2 = Bg + (long long)((tt)*16) * N; \
        da0 = *(const float4*)(Ag2); \
        da1 = *(const float4*)(Ag2 + (long long)64 * K); \
        db0 = *(const float4*)(Bg2); \
        db1 = *(const float4*)(Bg2 + (long long)8 * N); }

    const int nk = K >> 4;                 // 8 / 16 / 32 — always even

    float4 xa0,xa1,xb0,xb1;
    float4 ya0,ya1,yb0,yb1;

    {
        float4 p0,p1,p2,p3;
        LOADT(p0,p1,p2,p3, 0);
        stage_store(Asm, Bsm, ar,ac,br,bc, p0,p1,p2,p3);
        LOADT(ya0,ya1,yb0,yb1, 1);
    }
    __syncthreads();

    ull acc[4][8];
    #pragma unroll
    for(int r=0;r<4;r++){
        #pragma unroll
        for(int c=0;c<8;c++) acc[r][c]=0ull;
    }

    const int mb = wm*32 + lm*4;
    const int nb = wn*64 + ln*4;

    for(int t=0;t<nk;t+=2){
        const int s0 = t%3, s1 = (t+1)%3, s2 = (t+2)%3;
        if(t+2<nk) LOADT(xa0,xa1,xb0,xb1, t+2);
        gemm_block16(Asm + s0*AS_FLOATS, Bsm + s0*BS_FLOATS, mb, nb, acc);
        stage_store(Asm + s1*AS_FLOATS, Bsm + s1*BS_FLOATS, ar,ac,br,bc, ya0,ya1,yb0,yb1);
        __syncthreads();
        if(t+3<nk) LOADT(ya0,ya1,yb0,yb1, t+3);
        gemm_block16(Asm + s1*AS_FLOATS, Bsm + s1*BS_FLOATS, mb, nb, acc);
        if(t+2<nk) stage_store(Asm + s2*AS_FLOATS, Bsm + s2*BS_FLOATS, ar,ac,br,bc, xa0,xa1,xb0,xb1);
        __syncthreads();
    }
    #undef LOADT

    float bz[8];
    if(EPI){
        float4 q0 = *(const float4*)(bias + n0 + nb);
        float4 q1 = *(const float4*)(bias + n0 + nb + 32);
        bz[0]=q0.x; bz[1]=q0.y; bz[2]=q0.z; bz[3]=q0.w;
        bz[4]=q1.x; bz[5]=q1.y; bz[6]=q1.z; bz[7]=q1.w;
    }
    #pragma unroll
    for(int r=0;r<4;r++){
        const int row_lo = m0 + mb + (r&1)*2 + (r>>1)*16;
        float vl[8], vh[8];
        #pragma unroll
        for(int c=0;c<8;c++){
            float lo = lo2(acc[r][c]), hi = hi2(acc[r][c]);
            if(EPI){ lo = fmaxf(lo + bz[c], 0.f); hi = fmaxf(hi + bz[c], 0.f); }
            vl[c]=lo; vh[c]=hi;
        }
        float* c0 = C + (long long)(row_lo    ) * N + n0 + nb;
        float* c1 = C + (long long)(row_lo + 1) * N + n0 + nb;
        *(float4*)(c0)    = make_float4(vl[0],vl[1],vl[2],vl[3]);
        *(float4*)(c0+32) = make_float4(vl[4],vl[5],vl[6],vl[7]);
        *(float4*)(c1)    = make_float4(vh[0],vh[1],vh[2],vh[3]);
        *(float4*)(c1+32) = make_float4(vh[4],vh[5],vh[6],vh[7]);
    }
}

// ============================================================================
// graph kernel: Gram -> D2 -> RANK-BASED kNN (fully parallel, bit-identical
// to stable argsort selection) -> packed NmP -> Xagg = Nm @ Ap.
// D2 overlays the upper half of the per-sample G/NmP buffer (400 ull).
// ============================================================================
template<int IN, int NB>
__global__ void __launch_bounds__(256)
graph_kernel(const float* __restrict__ act, float* __restrict__ outp)
{
    extern __shared__ __align__(16) char gsm[];
    float*          Ap    = (float*)gsm;                          // NB*PNT*IN (40960B)
    ull*            bufA  = (ull*)(gsm + 40960);                  // NB*400 ull: G/D2 then NmP
    unsigned char*  rankA = (unsigned char*)(gsm + 40960 + NB*PNT*PNT*8);  // NB*400
    int*            deg   = (int*)(rankA + NB*PNT*PNT);
    float*          dinv  = (float*)(deg + NB*PNT);
    unsigned char*  pii   = (unsigned char*)(dinv + NB*PNT);
    unsigned char*  pjj   = pii + 210;

    const int tid = threadIdx.x, warp = tid >> 5, lane = tid & 31;
    const long long b0 = (long long)blockIdx.x * NB;

    if(tid < 210){
        int i=0, rem=tid;
        while(rem >= PNT-i){ rem -= PNT-i; i++; }
        pii[tid]=(unsigned char)i; pjj[tid]=(unsigned char)(i+rem);
    }
    {
        const float4* src4 = (const float4*)(act + b0*(long long)(PNT*IN));
        float4* Ap4 = (float4*)Ap;
        for(int q=tid;q<NB*PNT*IN/4;q+=256) Ap4[q]=src4[q];
    }
    if(tid<NB*PNT) deg[tid]=1;      // self loop
    __syncthreads();

    // Gram per sample: 210 pairs, 4 in flight per warp, packed f32x2 dots
    #pragma unroll
    for(int sb=0; sb<NB; sb++){
        const float* ApS = Ap + sb*(PNT*IN);
        float* G = (float*)(bufA + sb*(PNT*PNT));
        for(int q0 = warp*4; q0 < 210; q0 += 32){
            int ii[4], jj[4]; float accv[4];
            #pragma unroll
            for(int u=0;u<4;u++){
                int q = q0+u; if(q >= 210) q = 0;
                ii[u]=pii[q]; jj[u]=pjj[q];
            }
            #pragma unroll
            for(int u=0;u<4;u++){
                const ulonglong2* ri = (const ulonglong2*)&ApS[ii[u]*IN];
                const ulonglong2* rj = (const ulonglong2*)&ApS[jj[u]*IN];
                ull s0=0ull, s1=0ull;
                #pragma unroll
                for(int c=0;c<IN/128;c++){
                    ulonglong2 av = ri[lane + c*32], bv = rj[lane + c*32];
                    s0 = ffma2(av.x, bv.x, s0);
                    s1 = ffma2(av.y, bv.y, s1);
                }
                accv[u] = (lo2(s0)+hi2(s0)) + (lo2(s1)+hi2(s1));
            }
            #pragma unroll
            for(int u=0;u<4;u++) accv[u]=warp_sum(accv[u]);
            if(lane==0){
                #pragma unroll
                for(int u=0;u<4;u++) if(q0+u<210){
                    G[ii[u]*PNT+jj[u]] = accv[u];
                    G[jj[u]*PNT+ii[u]] = accv[u];
                }
            }
        }
    }
    __syncthreads();

    // D2[i][j] = gii + gjj - 2*Gij (EXACT same float expr/order as before);
    // self -> -inf. Stored in upper half of the per-sample ull buffer.
    for(int q=tid;q<NB*PNT*PNT;q+=256){
        int sb = q/(PNT*PNT), r = q%(PNT*PNT), i = r/PNT, j = r%PNT;
        const float* G = (const float*)(bufA + sb*(PNT*PNT));
        float* D2 = (float*)(bufA + sb*(PNT*PNT)) + PNT*PNT;
        D2[r] = (i==j) ? __int_as_float(0xff800000)
                       : G[i*PNT+i] + G[j*PNT+j] - 2.f*G[i*PNT+j];
    }
    __syncthreads();

    // rank[i][j] = #{j' : d2[i][j'] < d2[i][j] or (== and j' < j)}.
    // Ranks are a total order per row -> rank==stable-argsort position.
    // rank 0 = self (-inf); neighbors are rank 1..KNN. deg counted here.
    for(int q=tid;q<NB*PNT*PNT;q+=256){
        int sb = q/(PNT*PNT), r = q%(PNT*PNT), i = r/PNT, j = r%PNT;
        const float* D2 = (const float*)(bufA + sb*(PNT*PNT)) + PNT*PNT;
        const float dj = D2[i*PNT+j];
        int cnt=0;
        #pragma unroll
        for(int jp=0;jp<PNT;jp++){
            float v = D2[i*PNT+jp];
            cnt += (v < dj) || (v == dj && jp < j);
        }
        rankA[q] = (unsigned char)cnt;
        if(cnt>=1 && cnt<=KNN) atomicAdd(&deg[sb*PNT + j], 1);
    }
    __syncthreads();                        // D2 consumed; bufA becomes NmP

    if(tid<NB*PNT) dinv[tid] = rsqrtf((float)deg[tid]);
    for(int q=tid;q<NB*PNT*PNT;q+=256) bufA[q]=0ull;
    __syncthreads();

    // scatter edge weights: edge u=i (source) -> t=j (target), rank in [1,8]
    for(int q=tid;q<NB*PNT*PNT;q+=256){
        int rk = rankA[q];
        if(rk>=1 && rk<=KNN){
            int sb = q/(PNT*PNT), r = q%(PNT*PNT), i = r/PNT, j = r%PNT;
            float w = dinv[sb*PNT+j]*dinv[sb*PNT+i];
            bufA[sb*(PNT*PNT) + i*PNT + j] = pack2f(w,w);
        }
    }
    if(tid<NB*PNT){
        int sb = tid/PNT, p = tid%PNT;
        float w = dinv[tid]*dinv[tid];
        bufA[sb*(PNT*PNT) + p*PNT + p] = pack2f(w,w);
    }
    __syncthreads();

    // Xagg[t][f] = sum_s Nm[t][s]*Ap[s][f]; NmP rows read as ulonglong2
    {
        const int sb  = tid / (IN/2);        // warp-uniform (IN/2 >= 64)
        const int f2l = tid % (IN/2);
        const float* ApS = Ap + sb*(PNT*IN);
        const ull* NmP = bufA + sb*(PNT*PNT);
        ull acc[PNT];
        #pragma unroll
        for(int t=0;t<PNT;t++) acc[t]=0ull;
        #pragma unroll 2
        for(int s=0;s<PNT;s++){
            ull av = *(const ull*)&ApS[s*IN + 2*f2l];
            const ulonglong2* nrow2 = (const ulonglong2*)&NmP[s*PNT];
            #pragma unroll
            for(int t2=0;t2<PNT/2;t2++){
                ulonglong2 nv = nrow2[t2];       // broadcast LDS.128
                acc[2*t2  ] = ffma2(av, nv.x, acc[2*t2  ]);
                acc[2*t2+1] = ffma2(av, nv.y, acc[2*t2+1]);
            }
        }
        float* dst = outp + (b0+sb)*(long long)(PNT*IN);
        #pragma unroll
        for(int t=0;t<PNT;t++) *(ull*)&dst[t*IN + 2*f2l] = acc[t];
    }
}
#define GRAPH_SMEM(NB) (40960 + (NB)*PNT*PNT*8 + (NB)*PNT*PNT + (NB)*PNT*4 + (NB)*PNT*4 + 512)

// ============================================================================
// head: mean pool -> fc 128x64 relu -> fc 64x3 -> softmax
// ============================================================================
__global__ void __launch_bounds__(128)
head_kernel(const float* __restrict__ act,
            const float* __restrict__ W4, const float* __restrict__ b4,
            const float* __restrict__ W5, const float* __restrict__ b5,
            float* __restrict__ out)
{
    __shared__ float msm[128], hsm[64], lsm[3];
    const int tid = threadIdx.x;
    const long long b = blockIdx.x;
    const float* ab = act + b*(long long)(PNT*128);
    {
        float s=0.f;
        #pragma unroll
        for(int p=0;p<PNT;p++) s += ab[p*128 + tid];
        msm[tid] = s * (1.f/PNT);
    }
    __syncthreads();
    if(tid<64){
        float a=b4[tid];
        #pragma unroll 4
        for(int f=0;f<128;f++) a = fmaf(msm[f], W4[f*64+tid], a);
        hsm[tid]=fmaxf(a,0.f);
    }
    __syncthreads();
    if(tid<3){
        float a=b5[tid];
        #pragma unroll
        for(int j=0;j<64;j++) a = fmaf(hsm[j], W5[j*3+tid], a);
        lsm[tid]=a;
    }
    __syncthreads();
    if(tid==0){
        float l0=lsm[0], l1=lsm[1], l2=lsm[2];
        float m=fmaxf(l0,fmaxf(l1,l2));
        float e0=expf(l0-m), e1=expf(l1-m), e2=expf(l2-m);
        float s=e0+e1+e2;
        out[b*3+0]=e0/s; out[b*3+1]=e1/s; out[b*3+2]=e2/s;
    }
}

extern "C" void kernel_launch(void* const* d_in, const int* in_sizes, int n_in,
                              void* d_out, int out_size){
    const float* x  = (const float*)d_in[0];
    const float* W1 = (const float*)d_in[1];
    const float* b1 = (const float*)d_in[2];
    const float* W2 = (const float*)d_in[3];
    const float* b2 = (const float*)d_in[4];
    const float* W3 = (const float*)d_in[5];
    const float* b3 = (const float*)d_in[6];
    const float* W4 = (const float*)d_in[7];
    const float* b4 = (const float*)d_in[8];
    const float* W5 = (const float*)d_in[9];
    const float* b5 = (const float*)d_in[10];
    float* out = (float*)d_out;

    const int NS = in_sizes[0]/(PNT*D0);   // 8192
    const int M  = NS*PNT;                 // 163840

    float *act, *tmp;
    cudaGetSymbolAddress((void**)&act, g_act);
    cudaGetSymbolAddress((void**)&tmp, g_tmp);

    cudaFuncSetAttribute(sgemm_kernel<true>,
        cudaFuncAttributeMaxDynamicSharedMemorySize, SGEMM_SMEM);
    cudaFuncSetAttribute(graph_kernel<128,4>,
        cudaFuncAttributeMaxDynamicSharedMemorySize, GRAPH_SMEM(4));
    cudaFuncSetAttribute(graph_kernel<256,2>,
        cudaFuncAttributeMaxDynamicSharedMemorySize, GRAPH_SMEM(2));
    cudaFuncSetAttribute(graph_kernel<512,1>,
        cudaFuncAttributeMaxDynamicSharedMemorySize, GRAPH_SMEM(1));

    // layer 1: xagg = Nm@x, then GEMM+bias+relu (aggregate-before)
    graph_kernel<128,4><<<NS/4,256,GRAPH_SMEM(4)>>>(x, tmp);
    sgemm_kernel<true><<<dim3(2, M/128),256,SGEMM_SMEM>>>(tmp, W1, b1, act, M, 256, 128);
    // layer 2
    graph_kernel<256,2><<<NS/2,256,GRAPH_SMEM(2)>>>(act, tmp);
    sgemm_kernel<true><<<dim3(4, M/128),256,SGEMM_SMEM>>>(tmp, W2, b2, act, M, 512, 256);
    // layer 3
    graph_kernel<512,1><<<NS,256,GRAPH_SMEM(1)>>>(act, tmp);
    sgemm_kernel<true><<<dim3(1, M/128),256,SGEMM_SMEM>>>(tmp, W3, b3, act, M, 128, 512);
    // head
    head_kernel<<<NS,128>>>(act, W4, b4, W5, b5, out);
}

// round 16
// speedup vs baseline: 1.0566x; 1.0566x over previous
#include <cuda_runtime.h>
#include <math.h>

#define PNT 20
#define KNN 8
#define D0  128
#define MAXN 8192
typedef unsigned long long ull;

__device__ float g_act[ (size_t)MAXN*PNT*512 ];   // activations (widest 512)
__device__ float g_tmp[ (size_t)MAXN*PNT*512 ];   // xagg scratch (widest 512)

__device__ __forceinline__ ull pack2f(float x, float y){
    return ((ull)__float_as_uint(y) << 32) | (ull)__float_as_uint(x);
}
__device__ __forceinline__ ull ffma2(ull a, ull b, ull c){
    ull d;
    asm("fma.rn.f32x2 %0, %1, %2, %3;" : "=l"(d) : "l"(a), "l"(b), "l"(c));
    return d;
}
__device__ __forceinline__ float lo2(ull v){ return __uint_as_float((unsigned)(v & 0xffffffffull)); }
__device__ __forceinline__ float hi2(ull v){ return __uint_as_float((unsigned)(v >> 32)); }
__device__ __forceinline__ float warp_sum(float v){
    #pragma unroll
    for(int m=16;m>0;m>>=1) v += __shfl_xor_sync(0xffffffffu, v, m);
    return v;
}

// ============================================================================
// sgemm: FROZEN R14 version (746us on L2 shape, fma 72.9%).
// 128x128x16 tiles, triple-buffered smem, prefetch distance 2.
// ============================================================================
#define AS_FLOATS (16*132)
#define BS_FLOATS (16*128)
#define SGEMM_SMEM ((3*AS_FLOATS + 3*BS_FLOATS)*4)

__device__ __forceinline__ void gemm_block16(const float* __restrict__ Ab,
                                             const float* __restrict__ Bb,
                                             int mb, int nb, ull (&acc)[4][8]){
    #pragma unroll
    for(int k=0;k<16;k++){
        ulonglong2 a01 = *(const ulonglong2*)&Ab[k*132+mb];
        ulonglong2 a23 = *(const ulonglong2*)&Ab[k*132+mb+16];
        float4 q0 = *(const float4*)&Bb[k*128+nb];
        float4 q1 = *(const float4*)&Bb[k*128+nb+32];
        ull am[4] = {a01.x, a01.y, a23.x, a23.y};
        float bb[8] = {q0.x,q0.y,q0.z,q0.w, q1.x,q1.y,q1.z,q1.w};
        #pragma unroll
        for(int c=0;c<8;c++){
            ull w = pack2f(bb[c], bb[c]);
            #pragma unroll
            for(int r=0;r<4;r++) acc[r][c] = ffma2(am[r], w, acc[r][c]);
        }
    }
}

__device__ __forceinline__ void stage_store(float* __restrict__ Ab, float* __restrict__ Bb,
    int ar, int ac, int br, int bc,
    const float4& a0, const float4& a1, const float4& b0, const float4& b1){
    Ab[(ac+0)*132+ar] = a0.x; Ab[(ac+1)*132+ar] = a0.y;
    Ab[(ac+2)*132+ar] = a0.z; Ab[(ac+3)*132+ar] = a0.w;
    Ab[(ac+0)*132+ar+64] = a1.x; Ab[(ac+1)*132+ar+64] = a1.y;
    Ab[(ac+2)*132+ar+64] = a1.z; Ab[(ac+3)*132+ar+64] = a1.w;
    *(float4*)&Bb[br*128+bc]     = b0;
    *(float4*)&Bb[(br+8)*128+bc] = b1;
}

template<bool EPI>
__global__ void __launch_bounds__(256,2)
sgemm_kernel(const float* __restrict__ A, const float* __restrict__ B,
             const float* __restrict__ bias, float* __restrict__ C,
             int M, int N, int K)
{
    extern __shared__ __align__(16) char sg[];
    float* Asm = (float*)sg;                         // [3][16][132]
    float* Bsm = (float*)(sg + 3*AS_FLOATS*4);       // [3][16][128]

    const int tid = threadIdx.x;
    const int warp = tid >> 5, lane = tid & 31;
    const int wm = warp >> 1, wn = warp & 1;
    const int lm = lane & 3,  ln = lane >> 2;
    const int m0 = blockIdx.y * 128, n0 = blockIdx.x * 128;
    const int ar = tid >> 2, ac = (tid & 3) * 4;
    const int br = tid >> 5, bc = (tid & 31) * 4;

    const float* Ag = A + (long long)(m0 + ar) * K + ac;
    const float* Bg = B + (long long)br * N + (n0 + bc);

    #define LOADT(da0,da1,db0,db1,tt) { \
        const float* Ag2 = Ag + (tt)*16; \
        const float* Bg2 = Bg + (long long)((tt)*16) * N; \
        da0 = *(const float4*)(Ag2); \
        da1 = *(const float4*)(Ag2 + (long long)64 * K); \
        db0 = *(const float4*)(Bg2); \
        db1 = *(const float4*)(Bg2 + (long long)8 * N); }

    const int nk = K >> 4;                 // 8 / 16 / 32 — always even

    float4 xa0,xa1,xb0,xb1;
    float4 ya0,ya1,yb0,yb1;

    {
        float4 p0,p1,p2,p3;
        LOADT(p0,p1,p2,p3, 0);
        stage_store(Asm, Bsm, ar,ac,br,bc, p0,p1,p2,p3);
        LOADT(ya0,ya1,yb0,yb1, 1);
    }
    __syncthreads();

    ull acc[4][8];
    #pragma unroll
    for(int r=0;r<4;r++){
        #pragma unroll
        for(int c=0;c<8;c++) acc[r][c]=0ull;
    }

    const int mb = wm*32 + lm*4;
    const int nb = wn*64 + ln*4;

    for(int t=0;t<nk;t+=2){
        const int s0 = t%3, s1 = (t+1)%3, s2 = (t+2)%3;
        if(t+2<nk) LOADT(xa0,xa1,xb0,xb1, t+2);
        gemm_block16(Asm + s0*AS_FLOATS, Bsm + s0*BS_FLOATS, mb, nb, acc);
        stage_store(Asm + s1*AS_FLOATS, Bsm + s1*BS_FLOATS, ar,ac,br,bc, ya0,ya1,yb0,yb1);
        __syncthreads();
        if(t+3<nk) LOADT(ya0,ya1,yb0,yb1, t+3);
        gemm_block16(Asm + s1*AS_FLOATS, Bsm + s1*BS_FLOATS, mb, nb, acc);
        if(t+2<nk) stage_store(Asm + s2*AS_FLOATS, Bsm + s2*BS_FLOATS, ar,ac,br,bc, xa0,xa1,xb0,xb1);
        __syncthreads();
    }
    #undef LOADT

    float bz[8];
    if(EPI){
        float4 q0 = *(const float4*)(bias + n0 + nb);
        float4 q1 = *(const float4*)(bias + n0 + nb + 32);
        bz[0]=q0.x; bz[1]=q0.y; bz[2]=q0.z; bz[3]=q0.w;
        bz[4]=q1.x; bz[5]=q1.y; bz[6]=q1.z; bz[7]=q1.w;
    }
    #pragma unroll
    for(int r=0;r<4;r++){
        const int row_lo = m0 + mb + (r&1)*2 + (r>>1)*16;
        float vl[8], vh[8];
        #pragma unroll
        for(int c=0;c<8;c++){
            float lo = lo2(acc[r][c]), hi = hi2(acc[r][c]);
            if(EPI){ lo = fmaxf(lo + bz[c], 0.f); hi = fmaxf(hi + bz[c], 0.f); }
            vl[c]=lo; vh[c]=hi;
        }
        float* c0 = C + (long long)(row_lo    ) * N + n0 + nb;
        float* c1 = C + (long long)(row_lo + 1) * N + n0 + nb;
        *(float4*)(c0)    = make_float4(vl[0],vl[1],vl[2],vl[3]);
        *(float4*)(c0+32) = make_float4(vl[4],vl[5],vl[6],vl[7]);
        *(float4*)(c1)    = make_float4(vh[0],vh[1],vh[2],vh[3]);
        *(float4*)(c1+32) = make_float4(vh[4],vh[5],vh[6],vh[7]);
    }
}

// ============================================================================
// graph kernel: Gram (i-grouped: ri loaded once per 4 pairs) -> D2 ->
// rank-based kNN -> packed NmP -> Xagg (4-feature x 10-target thread tile).
// Per-pair / per-output arithmetic orders identical to R15 (bit-exact).
// ============================================================================
template<int IN, int NB>
__global__ void __launch_bounds__(256)
graph_kernel(const float* __restrict__ act, float* __restrict__ outp)
{
    extern __shared__ __align__(16) char gsm[];
    float*          Ap    = (float*)gsm;                          // NB*PNT*IN (40960B)
    ull*            bufA  = (ull*)(gsm + 40960);                  // NB*400 ull: G/D2 then NmP
    unsigned char*  rankA = (unsigned char*)(gsm + 40960 + NB*PNT*PNT*8);  // NB*400
    int*            deg   = (int*)(rankA + NB*PNT*PNT);
    float*          dinv  = (float*)(deg + NB*PNT);

    const int tid = threadIdx.x, warp = tid >> 5, lane = tid & 31;
    const long long b0 = (long long)blockIdx.x * NB;

    {
        const float4* src4 = (const float4*)(act + b0*(long long)(PNT*IN));
        float4* Ap4 = (float4*)Ap;
        for(int q=tid;q<NB*PNT*IN/4;q+=256) Ap4[q]=src4[q];
    }
    if(tid<NB*PNT) deg[tid]=1;      // self loop
    __syncthreads();

    // Gram, i-grouped: warp takes rows i = warp, warp+8, ...; for each i,
    // 4 pairs (i, j0..j0+3) share the ri load. Per c-iter: 5 LDS.128 + 8 ffma2.
    #pragma unroll
    for(int sb=0; sb<NB; sb++){
        const float* ApS = Ap + sb*(PNT*IN);
        float* G = (float*)(bufA + sb*(PNT*PNT));
        for(int i = warp; i < PNT; i += 8){
            const ulonglong2* ri = (const ulonglong2*)&ApS[i*IN];
            for(int j0 = i; j0 < PNT; j0 += 4){
                int jj[4];
                #pragma unroll
                for(int u=0;u<4;u++){ int j=j0+u; jj[u] = (j<PNT) ? j : i; }
                const ulonglong2* rj0 = (const ulonglong2*)&ApS[jj[0]*IN];
                const ulonglong2* rj1 = (const ulonglong2*)&ApS[jj[1]*IN];
                const ulonglong2* rj2 = (const ulonglong2*)&ApS[jj[2]*IN];
                const ulonglong2* rj3 = (const ulonglong2*)&ApS[jj[3]*IN];
                ull s0a=0,s0b=0, s1a=0,s1b=0, s2a=0,s2b=0, s3a=0,s3b=0;
                #pragma unroll
                for(int c=0;c<IN/128;c++){
                    ulonglong2 av = ri[lane + c*32];
                    ulonglong2 b0v = rj0[lane + c*32];
                    ulonglong2 b1v = rj1[lane + c*32];
                    ulonglong2 b2v = rj2[lane + c*32];
                    ulonglong2 b3v = rj3[lane + c*32];
                    s0a = ffma2(av.x, b0v.x, s0a); s0b = ffma2(av.y, b0v.y, s0b);
                    s1a = ffma2(av.x, b1v.x, s1a); s1b = ffma2(av.y, b1v.y, s1b);
                    s2a = ffma2(av.x, b2v.x, s2a); s2b = ffma2(av.y, b2v.y, s2b);
                    s3a = ffma2(av.x, b3v.x, s3a); s3b = ffma2(av.y, b3v.y, s3b);
                }
                float accv[4];
                accv[0] = (lo2(s0a)+hi2(s0a)) + (lo2(s0b)+hi2(s0b));
                accv[1] = (lo2(s1a)+hi2(s1a)) + (lo2(s1b)+hi2(s1b));
                accv[2] = (lo2(s2a)+hi2(s2a)) + (lo2(s2b)+hi2(s2b));
                accv[3] = (lo2(s3a)+hi2(s3a)) + (lo2(s3b)+hi2(s3b));
                #pragma unroll
                for(int u=0;u<4;u++) accv[u]=warp_sum(accv[u]);
                if(lane==0){
                    #pragma unroll
                    for(int u=0;u<4;u++) if(j0+u<PNT){
                        G[i*PNT+jj[u]] = accv[u];
                        G[jj[u]*PNT+i] = accv[u];
                    }
                }
            }
        }
    }
    __syncthreads();

    // D2[i][j] = gii + gjj - 2*Gij (EXACT same float expr as before); self -> -inf
    for(int q=tid;q<NB*PNT*PNT;q+=256){
        int sb = q/(PNT*PNT), r = q%(PNT*PNT), i = r/PNT, j = r%PNT;
        const float* G = (const float*)(bufA + sb*(PNT*PNT));
        float* D2 = (float*)(bufA + sb*(PNT*PNT)) + PNT*PNT;
        D2[r] = (i==j) ? __int_as_float(0xff800000)
                       : G[i*PNT+i] + G[j*PNT+j] - 2.f*G[i*PNT+j];
    }
    __syncthreads();

    // rank-based stable selection: rank==stable-argsort position.
    for(int q=tid;q<NB*PNT*PNT;q+=256){
        int sb = q/(PNT*PNT), r = q%(PNT*PNT), i = r/PNT, j = r%PNT;
        const float* D2 = (const float*)(bufA + sb*(PNT*PNT)) + PNT*PNT;
        const float dj = D2[i*PNT+j];
        int cnt=0;
        #pragma unroll
        for(int jp=0;jp<PNT;jp++){
            float v = D2[i*PNT+jp];
            cnt += (v < dj) || (v == dj && jp < j);
        }
        rankA[q] = (unsigned char)cnt;
        if(cnt>=1 && cnt<=KNN) atomicAdd(&deg[sb*PNT + j], 1);
    }
    __syncthreads();                        // D2 consumed; bufA becomes NmP

    if(tid<NB*PNT) dinv[tid] = rsqrtf((float)deg[tid]);
    for(int q=tid;q<NB*PNT*PNT;q+=256) bufA[q]=0ull;
    __syncthreads();

    // scatter edge weights: edge u=i (source) -> t=j (target), rank in [1,8]
    for(int q=tid;q<NB*PNT*PNT;q+=256){
        int rk = rankA[q];
        if(rk>=1 && rk<=KNN){
            int sb = q/(PNT*PNT), r = q%(PNT*PNT), i = r/PNT, j = r%PNT;
            float w = dinv[sb*PNT+j]*dinv[sb*PNT+i];
            bufA[sb*(PNT*PNT) + i*PNT + j] = pack2f(w,w);
        }
    }
    if(tid<NB*PNT){
        int sb = tid/PNT, p = tid%PNT;
        float w = dinv[tid]*dinv[tid];
        bufA[sb*(PNT*PNT) + p*PNT + p] = pack2f(w,w);
    }
    __syncthreads();

    // Xagg: thread = (sb, feature-quad fq, t-half th). Per s: 1 LDS.128 (av,
    // 4 features) + 5 LDS.128 (Nm pairs, warp-broadcast) + 20 ffma2.
    // Output order per (t,f): s ascending -> bit-identical to before.
    {
        const int sb  = tid / (IN/2);            // warp-uniform (IN/2 >= 64)
        const int rem = tid % (IN/2);
        const int fq  = rem % (IN/4);            // 4 features: 4fq..4fq+3
        const int th  = rem / (IN/4);            // t-half: 0 -> t 0..9, 1 -> 10..19
        const float* ApS = Ap + sb*(PNT*IN);
        const ull* NmP = bufA + sb*(PNT*PNT);
        ull acc[10][2];
        #pragma unroll
        for(int tt=0;tt<10;tt++){ acc[tt][0]=0ull; acc[tt][1]=0ull; }
        #pragma unroll 2
        for(int s=0;s<PNT;s++){
            ulonglong2 av = *(const ulonglong2*)&ApS[s*IN + 4*fq];
            const ulonglong2* nrow2 = (const ulonglong2*)&NmP[s*PNT];
            #pragma unroll
            for(int t2=0;t2<5;t2++){
                ulonglong2 nv = nrow2[th*5 + t2];   // broadcast LDS.128
                acc[2*t2  ][0] = ffma2(av.x, nv.x, acc[2*t2  ][0]);
                acc[2*t2  ][1] = ffma2(av.y, nv.x, acc[2*t2  ][1]);
                acc[2*t2+1][0] = ffma2(av.x, nv.y, acc[2*t2+1][0]);
                acc[2*t2+1][1] = ffma2(av.y, nv.y, acc[2*t2+1][1]);
            }
        }
        float* dst = outp + (b0+sb)*(long long)(PNT*IN);
        #pragma unroll
        for(int tt=0;tt<10;tt++){
            int t = th*10 + tt;
            *(ulonglong2*)&dst[t*IN + 4*fq] = make_ulonglong2(acc[tt][0], acc[tt][1]);
        }
    }
}
#define GRAPH_SMEM(NB) (40960 + (NB)*PNT*PNT*8 + (NB)*PNT*PNT + (NB)*PNT*4 + (NB)*PNT*4 + 512)

// ============================================================================
// head: mean pool -> fc 128x64 relu -> fc 64x3 -> softmax
// ============================================================================
__global__ void __launch_bounds__(128)
head_kernel(const float* __restrict__ act,
            const float* __restrict__ W4, const float* __restrict__ b4,
            const float* __restrict__ W5, const float* __restrict__ b5,
            float* __restrict__ out)
{
    __shared__ float msm[128], hsm[64], lsm[3];
    const int tid = threadIdx.x;
    const long long b = blockIdx.x;
    const float* ab = act + b*(long long)(PNT*128);
    {
        float s=0.f;
        #pragma unroll
        for(int p=0;p<PNT;p++) s += ab[p*128 + tid];
        msm[tid] = s * (1.f/PNT);
    }
    __syncthreads();
    if(tid<64){
        float a=b4[tid];
        #pragma unroll 4
        for(int f=0;f<128;f++) a = fmaf(msm[f], W4[f*64+tid], a);
        hsm[tid]=fmaxf(a,0.f);
    }
    __syncthreads();
    if(tid<3){
        float a=b5[tid];
        #pragma unroll
        for(int j=0;j<64;j++) a = fmaf(hsm[j], W5[j*3+tid], a);
        lsm[tid]=a;
    }
    __syncthreads();
    if(tid==0){
        float l0=lsm[0], l1=lsm[1], l2=lsm[2];
        float m=fmaxf(l0,fmaxf(l1,l2));
        float e0=expf(l0-m), e1=expf(l1-m), e2=expf(l2-m);
        float s=e0+e1+e2;
        out[b*3+0]=e0/s; out[b*3+1]=e1/s; out[b*3+2]=e2/s;
    }
}

extern "C" void kernel_launch(void* const* d_in, const int* in_sizes, int n_in,
                              void* d_out, int out_size){
    const float* x  = (const float*)d_in[0];
    const float* W1 = (const float*)d_in[1];
    const float* b1 = (const float*)d_in[2];
    const float* W2 = (const float*)d_in[3];
    const float* b2 = (const float*)d_in[4];
    const float* W3 = (const float*)d_in[5];
    const float* b3 = (const float*)d_in[6];
    const float* W4 = (const float*)d_in[7];
    const float* b4 = (const float*)d_in[8];
    const float* W5 = (const float*)d_in[9];
    const float* b5 = (const float*)d_in[10];
    float* out = (float*)d_out;

    const int NS = in_sizes[0]/(PNT*D0);   // 8192
    const int M  = NS*PNT;                 // 163840

    float *act, *tmp;
    cudaGetSymbolAddress((void**)&act, g_act);
    cudaGetSymbolAddress((void**)&tmp, g_tmp);

    cudaFuncSetAttribute(sgemm_kernel<true>,
        cudaFuncAttributeMaxDynamicSharedMemorySize, SGEMM_SMEM);
    cudaFuncSetAttribute(graph_kernel<128,4>,
        cudaFuncAttributeMaxDynamicSharedMemorySize, GRAPH_SMEM(4));
    cudaFuncSetAttribute(graph_kernel<256,2>,
        cudaFuncAttributeMaxDynamicSharedMemorySize, GRAPH_SMEM(2));
    cudaFuncSetAttribute(graph_kernel<512,1>,
        cudaFuncAttributeMaxDynamicSharedMemorySize, GRAPH_SMEM(1));

    // layer 1: xagg = Nm@x, then GEMM+bias+relu (aggregate-before)
    graph_kernel<128,4><<<NS/4,256,GRAPH_SMEM(4)>>>(x, tmp);
    sgemm_kernel<true><<<dim3(2, M/128),256,SGEMM_SMEM>>>(tmp, W1, b1, act, M, 256, 128);
    // layer 2
    graph_kernel<256,2><<<NS/2,256,GRAPH_SMEM(2)>>>(act, tmp);
    sgemm_kernel<true><<<dim3(4, M/128),256,SGEMM_SMEM>>>(tmp, W2, b2, act, M, 512, 256);
    // layer 3
    graph_kernel<512,1><<<NS,256,GRAPH_SMEM(1)>>>(act, tmp);
    sgemm_kernel<true><<<dim3(1, M/128),256,SGEMM_SMEM>>>(tmp, W3, b3, act, M, 128, 512);
    // head
    head_kernel<<<NS,128>>>(act, W4, b4, W5, b5, out);
}